// round 14
// baseline (speedup 1.0000x reference)
#include <cuda_runtime.h>
#include <cstdint>

typedef unsigned long long ull;
typedef unsigned int uint;

#define D_MODEL 2048
#define N_STATE 256
#define RANK    64
#define LEVELS  8
#define MAX_T   16384

#define E_CTAS 8
#define E_ROWS 8
#define E_SMEM ((N_STATE * RANK + E_ROWS * N_STATE) * (int)sizeof(float))

#define RSB 36         // B smem row stride in ull (32 data + 4 pad)
#define UST 68         // u smem row stride in floats (64 data + 4 pad)

// ---- gemm1 pipeline ----
#define NSTAGE 3
#define U_STAGE_B (64 * UST * 4)              // 17408
#define B_STAGE_B (64 * RSB * 8)              // 18432
#define STAGE_B   (U_STAGE_B + B_STAGE_B)     // 35840
#define G1_SMEM   (NSTAGE * STAGE_B)          // 107520

// ---- gemm2 smem: A + 2x B(64-col chunk) + Dsm ----
#define G2A_B  (64 * RSB * 8)                 // 18432
#define G2B1_B (64 * RSB * 8)                 // 18432
#define G2D_F  (64 * 68)                      // Dsm floats
#define G2_SMEM (G2A_B + 2 * G2B1_B + G2D_F * 4)   // 72704
#define G2_CHUNKS 8                           // 8 col chunks of 64 (512 cols/CTA)

// scratch (plain, unpermuted layouts)
__device__ float g_E[RANK * RANK];
__device__ ull g_F1t[RANK * (D_MODEL / 2)];     // [n][kw] (hi bf16x2 | lo<<32)
__device__ ull g_Wt[D_MODEL * (RANK / 2)];      // [n][kw], Wt[n][k]=Wcm[k][n]
__device__ ull g_t[MAX_T * (RANK / 2)];         // [row][kw]

// =====================================================================
// helpers
// =====================================================================
__device__ __forceinline__ ull split2(float x0, float x1) {
    uint hh;
    asm("cvt.rn.bf16x2.f32 %0, %1, %2;" : "=r"(hh) : "f"(x1), "f"(x0));
    float h0 = __uint_as_float(hh << 16);
    float h1 = __uint_as_float(hh & 0xffff0000u);
    uint ll;
    asm("cvt.rn.bf16x2.f32 %0, %1, %2;" : "=r"(ll) : "f"(x1 - h1), "f"(x0 - h0));
    return (ull)hh | ((ull)ll << 32);
}

__device__ __forceinline__ void mma16816(float* d, uint a0, uint a1, uint a2, uint a3,
                                         uint b0, uint b1) {
    asm volatile(
        "mma.sync.aligned.m16n8k16.row.col.f32.bf16.bf16.f32 "
        "{%0,%1,%2,%3}, {%4,%5,%6,%7}, {%8,%9}, {%0,%1,%2,%3};"
        : "+f"(d[0]), "+f"(d[1]), "+f"(d[2]), "+f"(d[3])
        : "r"(a0), "r"(a1), "r"(a2), "r"(a3), "r"(b0), "r"(b1));
}

__device__ __forceinline__ uint smem_u32(const void* p) {
    uint a;
    asm("{ .reg .u64 t; cvta.to.shared.u64 t, %1; cvt.u32.u64 %0, t; }" : "=r"(a) : "l"(p));
    return a;
}
__device__ __forceinline__ void cp_async16(uint dst, const void* src) {
    asm volatile("cp.async.cg.shared.global [%0], [%1], 16;" :: "r"(dst), "l"(src));
}
#define CP_COMMIT() asm volatile("cp.async.commit_group;" ::: "memory")
#define CP_WAIT(n)  asm volatile("cp.async.wait_group %0;" :: "n"(n) : "memory")

// =====================================================================
// Kernel 0: E = Wbs @ Butterfly @ Wcr   (64x64)
// =====================================================================
__global__ __launch_bounds__(256) void compute_E_kernel(const float* __restrict__ A_factors,
                                                        const float* __restrict__ Wbs,
                                                        const float* __restrict__ Wcr) {
    extern __shared__ float esm[];
    float* Wcr_s = esm;
    float* G     = esm + N_STATE * RANK;
    __shared__ float Af[LEVELS * 4];
    const int tid = threadIdx.x;
    const int r0 = blockIdx.x * E_ROWS;
    if (tid < LEVELS * 4) Af[tid] = A_factors[tid];

    for (int i = tid; i < N_STATE * RANK / 4; i += 256)
        ((float4*)Wcr_s)[i] = ((const float4*)Wcr)[i];
    for (int i = tid; i < E_ROWS * N_STATE / 4; i += 256)
        ((float4*)G)[i] = ((const float4*)(Wbs + (size_t)r0 * N_STATE))[i];
    __syncthreads();

#pragma unroll
    for (int lvl = 0; lvl < LEVELS; lvl++) {
        const int stride = 128 >> lvl;
        const float a00 = Af[lvl * 4 + 0], a01 = Af[lvl * 4 + 1];
        const float a10 = Af[lvl * 4 + 2], a11 = Af[lvl * 4 + 3];
#pragma unroll
        for (int p = tid; p < E_ROWS * 128; p += 256) {
            int r  = p >> 7;
            int pi = p & 127;
            int low = pi & (stride - 1);
            int n0  = ((pi - low) << 1) | low;
            int n1  = n0 + stride;
            float x0 = G[r * N_STATE + n0];
            float x1 = G[r * N_STATE + n1];
            G[r * N_STATE + n0] = x0 * a00 + x1 * a10;
            G[r * N_STATE + n1] = x0 * a01 + x1 * a11;
        }
        __syncthreads();
    }

    for (int o = tid; o < E_ROWS * RANK; o += 256) {
        int r = o >> 6, j = o & 63;
        float acc = 0.f;
#pragma unroll 8
        for (int n = 0; n < N_STATE; n++)
            acc += G[r * N_STATE + n] * Wcr_s[n * RANK + j];
        g_E[(r0 + r) * RANK + j] = acc;
    }
}

// =====================================================================
// Kernel 1: F1t[n][kw] = hi/lo split of (Wbr @ E)^T. (conflict-free)
// =====================================================================
__global__ __launch_bounds__(256) void compute_F1t_kernel(const float* __restrict__ Wbr) {
    __shared__ float Wst[64 * 65];   // [r][k_local]
    __shared__ float Es[64 * 64];
    __shared__ float Fs[64 * 65];    // [n][k_local]
    const int tid = threadIdx.x;
    const int k0 = blockIdx.x * 64;

#pragma unroll
    for (int i = 0; i < 16; i++) {
        int idx = tid + i * 256;
        int k = idx >> 6, r = idx & 63;
        Wst[r * 65 + k] = Wbr[(size_t)(k0 + k) * 64 + r];
    }
#pragma unroll
    for (int i = 0; i < 4; i++)
        ((float4*)Es)[tid + i * 256] = ((const float4*)g_E)[tid + i * 256];
    __syncthreads();

    const int k = tid & 63, nq = tid >> 6;
#pragma unroll
    for (int nn = 0; nn < 16; nn++) {
        int n = nq * 16 + nn;
        float acc = 0.f;
#pragma unroll 8
        for (int r = 0; r < 64; r++)
            acc += Wst[r * 65 + k] * Es[r * 64 + n];
        Fs[n * 65 + k] = acc;
    }
    __syncthreads();

#pragma unroll
    for (int i = 0; i < 8; i++) {
        int idx = tid + i * 256;
        int n = idx >> 5, kw = idx & 31;
        g_F1t[(size_t)n * (D_MODEL / 2) + blockIdx.x * 32 + kw] =
            split2(Fs[n * 65 + 2 * kw], Fs[n * 65 + 2 * kw + 1]);
    }
}

// =====================================================================
// Kernel 1b: Wt[n][kw] = hi/lo split of Wcm^T.
// =====================================================================
__global__ __launch_bounds__(256) void compute_Wcmt_kernel(const float* __restrict__ Wcm) {
    __shared__ float S[64 * 65];
    const int tid = threadIdx.x;
    const int n0 = blockIdx.x * 64;
#pragma unroll
    for (int it = 0; it < 16; it++) {
        int idx = it * 256 + tid;
        int k = idx >> 6, nn = idx & 63;
        S[nn * 65 + k] = Wcm[(size_t)k * D_MODEL + n0 + nn];
    }
    __syncthreads();
#pragma unroll
    for (int it = 0; it < 8; it++) {
        int idx = it * 256 + tid;
        int nn = idx >> 5, kw = idx & 31;
        g_Wt[(size_t)(n0 + nn) * 32 + kw] = split2(S[nn * 65 + 2 * kw], S[nn * 65 + 2 * kw + 1]);
    }
}

// =====================================================================
// Kernel 2: GEMM1: t = u @ F1.  [R10/R12 version, measured 58us]
// =====================================================================
__global__ __launch_bounds__(256) void gemm1_mma(const float* __restrict__ u) {
    extern __shared__ char dsm[];
    const int tid = threadIdx.x;
    const int lane = tid & 31;
    const int w = tid >> 5;                  // 0..7
    const int g = lane >> 2, c = lane & 3;
    const int m0 = (w & 3) * 16;
    const int kpar = w >> 2;                 // 0: even chunks, 1: odd chunks
    const size_t row0 = (size_t)blockIdx.x * 64;

    const uint sbase = smem_u32(dsm);
    const int lr = tid >> 4, lseg = tid & 15;

    float acc[8][4];
#pragma unroll
    for (int i = 0; i < 8; i++)
#pragma unroll
        for (int j = 0; j < 4; j++) acc[i][j] = 0.f;

    auto issue = [&](int ch, int s) {
        const uint ub = sbase + (uint)s * STAGE_B;
        const uint bb = ub + U_STAGE_B;
        const float* usrc = u + (row0 + lr) * D_MODEL + ch * 64 + lseg * 4;
        const ull* bsrc = g_F1t + (size_t)lr * (D_MODEL / 2) + ch * 32 + lseg * 2;
#pragma unroll
        for (int j = 0; j < 4; j++) {
            cp_async16(ub + (uint)((lr + j * 16) * UST * 4 + lseg * 16),
                       usrc + (size_t)(j * 16) * D_MODEL);
            cp_async16(bb + (uint)((lr + j * 16) * RSB * 8 + lseg * 16),
                       bsrc + (size_t)(j * 16) * (D_MODEL / 2));
        }
        CP_COMMIT();
    };

    issue(0, 0);
    issue(1, 1);

    for (int ch = 0; ch < 32; ch++) {
        CP_WAIT(NSTAGE - 2);
        __syncthreads();
        if (ch + NSTAGE - 1 < 32) issue(ch + NSTAGE - 1, (ch + NSTAGE - 1) % NSTAGE);

        if ((ch & 1) == kpar) {
            const float* Us = (const float*)(dsm + (ch % NSTAGE) * STAGE_B);
            const ull* Bs = (const ull*)(dsm + (ch % NSTAGE) * STAGE_B + U_STAGE_B);
#pragma unroll
            for (int ks = 0; ks < 4; ks++) {
                float2 f0 = *(const float2*)&Us[(m0 + g) * UST + ks * 16 + c * 2];
                float2 f1 = *(const float2*)&Us[(m0 + g + 8) * UST + ks * 16 + c * 2];
                float2 f2 = *(const float2*)&Us[(m0 + g) * UST + ks * 16 + 8 + c * 2];
                float2 f3 = *(const float2*)&Us[(m0 + g + 8) * UST + ks * 16 + 8 + c * 2];
                ull A0 = split2(f0.x, f0.y), A1 = split2(f1.x, f1.y);
                ull A2 = split2(f2.x, f2.y), A3 = split2(f3.x, f3.y);
                uint ah0 = (uint)A0, al0 = (uint)(A0 >> 32);
                uint ah1 = (uint)A1, al1 = (uint)(A1 >> 32);
                uint ah2 = (uint)A2, al2 = (uint)(A2 >> 32);
                uint ah3 = (uint)A3, al3 = (uint)(A3 >> 32);
#pragma unroll
                for (int nh = 0; nh < 2; nh++) {
                    ull b0[4], b1[4];
#pragma unroll
                    for (int i = 0; i < 4; i++) {
                        int nt = nh * 4 + i;
                        b0[i] = Bs[(nt * 8 + g) * RSB + ks * 8 + c];
                        b1[i] = Bs[(nt * 8 + g) * RSB + ks * 8 + 4 + c];
                    }
#pragma unroll
                    for (int i = 0; i < 4; i++)
                        mma16816(acc[nh * 4 + i], ah0, ah1, ah2, ah3,
                                 (uint)b0[i], (uint)b1[i]);
#pragma unroll
                    for (int i = 0; i < 4; i++)
                        mma16816(acc[nh * 4 + i], ah0, ah1, ah2, ah3,
                                 (uint)(b0[i] >> 32), (uint)(b1[i] >> 32));
#pragma unroll
                    for (int i = 0; i < 4; i++)
                        mma16816(acc[nh * 4 + i], al0, al1, al2, al3,
                                 (uint)b0[i], (uint)b1[i]);
                }
            }
        }
    }

    // combine K-parity partials (padded stride 33 -> conflict-free)
    float* Red = (float*)dsm;
    if (kpar == 1) {
#pragma unroll
        for (int nt = 0; nt < 8; nt++)
#pragma unroll
            for (int j = 0; j < 4; j++)
                Red[((w & 3) * 32 + lane) * 33 + nt * 4 + j] = acc[nt][j];
    }
    __syncthreads();
    if (kpar == 0) {
#pragma unroll
        for (int nt = 0; nt < 8; nt++)
#pragma unroll
            for (int j = 0; j < 4; j++)
                acc[nt][j] += Red[((w & 3) * 32 + lane) * 33 + nt * 4 + j];

#pragma unroll
        for (int nt = 0; nt < 8; nt++) {
            int kw = nt * 4 + c;
            size_t r = row0 + m0 + g;
            g_t[r * 32 + kw]       = split2(acc[nt][0], acc[nt][1]);
            g_t[(r + 8) * 32 + kw] = split2(acc[nt][2], acc[nt][3]);
        }
    }
}

// =====================================================================
// Kernel 3: GEMM2: out = t @ Wcm + D*u.
// R14: per-CTA pipelined sweep over 8 column chunks of 64 (512 cols).
// A (t tile) resident + fragments loaded ONCE; B double-buffered via
// cp.async overlapping MMA+epilogue; Dsm-staged coalesced epilogue with
// batched u loads. grid = 256 row-tiles x 4 col-groups = 1024.
// =====================================================================
__global__ __launch_bounds__(256) void gemm2_mma(const float* __restrict__ u,
                                                 const float* __restrict__ Dv,
                                                 float* __restrict__ out) {
    extern __shared__ char dsm[];
    ull* Asm = (ull*)dsm;                               // [64 * RSB]
    ull* Bbuf0 = (ull*)(dsm + G2A_B);                   // [64 * RSB]
    ull* Bbuf1 = (ull*)(dsm + G2A_B + G2B1_B);          // [64 * RSB]
    float* Dsm = (float*)(dsm + G2A_B + 2 * G2B1_B);    // [64][68]

    const int tid = threadIdx.x;
    const int lane = tid & 31;
    const int w = tid >> 5;
    const int g = lane >> 2, c = lane & 3;
    const int m0 = (w & 3) * 16;
    const int n0b = (w >> 2) * 32;          // warp's 32-col slice of the 64-chunk
    const int cg = blockIdx.x & 3;
    const int rt = blockIdx.x >> 2;
    const size_t row0 = (size_t)rt * 64;
    const int colbase = cg * 512;

    const uint ab = smem_u32(Asm);
    const uint bb0 = smem_u32(Bbuf0);
    const uint bb1 = smem_u32(Bbuf1);
    const int lr4 = tid >> 4, lseg = tid & 15;   // staging mapping

    // issue B chunk cc into buffer buf
    auto issueB = [&](int cc, uint bb) {
#pragma unroll
        for (int j = 0; j < 4; j++) {
            int r = lr4 + j * 16;
            cp_async16(bb + (uint)(r * RSB * 8 + lseg * 16),
                       g_Wt + (size_t)(colbase + cc * 64 + r) * 32 + lseg * 2);
        }
        CP_COMMIT();
    };

    // group 0: A + B[0]
    {
#pragma unroll
        for (int j = 0; j < 4; j++) {
            int r = lr4 + j * 16;
            cp_async16(ab + (uint)(r * RSB * 8 + lseg * 16),
                       g_t + (row0 + r) * 32 + lseg * 2);
            cp_async16(bb0 + (uint)(r * RSB * 8 + lseg * 16),
                       g_Wt + (size_t)(colbase + r) * 32 + lseg * 2);
        }
        CP_COMMIT();
    }
    // group 1: B[1]
    issueB(1, bb1);
    CP_WAIT(1);          // A + B[0] ready
    __syncthreads();

    // A fragments once (reused for all 8 chunks)
    ull afr[16];
#pragma unroll
    for (int ks = 0; ks < 4; ks++) {
        afr[ks * 4 + 0] = Asm[(m0 + g) * RSB + ks * 8 + c];
        afr[ks * 4 + 1] = Asm[(m0 + g + 8) * RSB + ks * 8 + c];
        afr[ks * 4 + 2] = Asm[(m0 + g) * RSB + ks * 8 + 4 + c];
        afr[ks * 4 + 3] = Asm[(m0 + g + 8) * RSB + ks * 8 + 4 + c];
    }

    const int er = tid >> 2, eq = tid & 3;   // epilogue: row, 16-col quarter

    for (int cc = 0; cc < G2_CHUNKS; cc++) {
        const ull* Bs = (cc & 1) ? Bbuf1 : Bbuf0;

        float acc[4][4];
#pragma unroll
        for (int i = 0; i < 4; i++)
#pragma unroll
            for (int j = 0; j < 4; j++) acc[i][j] = 0.f;

#pragma unroll
        for (int ks = 0; ks < 4; ks++) {
            uint ah0 = (uint)afr[ks * 4 + 0], al0 = (uint)(afr[ks * 4 + 0] >> 32);
            uint ah1 = (uint)afr[ks * 4 + 1], al1 = (uint)(afr[ks * 4 + 1] >> 32);
            uint ah2 = (uint)afr[ks * 4 + 2], al2 = (uint)(afr[ks * 4 + 2] >> 32);
            uint ah3 = (uint)afr[ks * 4 + 3], al3 = (uint)(afr[ks * 4 + 3] >> 32);
            ull b0[4], b1[4];
#pragma unroll
            for (int nt = 0; nt < 4; nt++) {
                b0[nt] = Bs[(n0b + nt * 8 + g) * RSB + ks * 8 + c];
                b1[nt] = Bs[(n0b + nt * 8 + g) * RSB + ks * 8 + 4 + c];
            }
#pragma unroll
            for (int nt = 0; nt < 4; nt++)
                mma16816(acc[nt], ah0, ah1, ah2, ah3, (uint)b0[nt], (uint)b1[nt]);
#pragma unroll
            for (int nt = 0; nt < 4; nt++)
                mma16816(acc[nt], ah0, ah1, ah2, ah3,
                         (uint)(b0[nt] >> 32), (uint)(b1[nt] >> 32));
#pragma unroll
            for (int nt = 0; nt < 4; nt++)
                mma16816(acc[nt], al0, al1, al2, al3, (uint)b0[nt], (uint)b1[nt]);
        }

        // stage accumulators into Dsm (cols within chunk: n0b + nt*8 + c*2)
#pragma unroll
        for (int nt = 0; nt < 4; nt++) {
            int ccol = n0b + nt * 8 + c * 2;
            *(float2*)&Dsm[(m0 + g) * 68 + ccol]     = make_float2(acc[nt][0], acc[nt][1]);
            *(float2*)&Dsm[(m0 + g + 8) * 68 + ccol] = make_float2(acc[nt][2], acc[nt][3]);
        }

        // batch u + Dv loads for this chunk (overlaps sync + B issue)
        const int gc0 = colbase + cc * 64 + eq * 16;
        float4 dv[4], uv[4];
#pragma unroll
        for (int jj = 0; jj < 4; jj++) {
            dv[jj] = *(const float4*)(Dv + gc0 + jj * 4);
            uv[jj] = *(const float4*)(u + (row0 + er) * D_MODEL + gc0 + jj * 4);
        }

        __syncthreads();   // Dsm staged AND all warps done reading Bs

        if (cc + 2 < G2_CHUNKS) issueB(cc + 2, (cc & 1) ? bb1 : bb0);

        // epilogue: out = Dsm + D*u (coalesced float4)
#pragma unroll
        for (int jj = 0; jj < 4; jj++) {
            float4 o;
            o.x = Dsm[er * 68 + eq * 16 + jj * 4 + 0] + dv[jj].x * uv[jj].x;
            o.y = Dsm[er * 68 + eq * 16 + jj * 4 + 1] + dv[jj].y * uv[jj].y;
            o.z = Dsm[er * 68 + eq * 16 + jj * 4 + 2] + dv[jj].z * uv[jj].z;
            o.w = Dsm[er * 68 + eq * 16 + jj * 4 + 3] + dv[jj].w * uv[jj].w;
            *(float4*)(out + (row0 + er) * D_MODEL + gc0 + jj * 4) = o;
        }

        if (cc + 1 < G2_CHUNKS) {
            if (cc + 2 < G2_CHUNKS) { CP_WAIT(1); } else { CP_WAIT(0); }
            __syncthreads();   // B[cc+1] ready; Dsm reads done before rewrite
        }
    }
}

extern "C" void kernel_launch(void* const* d_in, const int* in_sizes, int n_in,
                              void* d_out, int out_size) {
    const float* u   = (const float*)d_in[0];
    const float* Af  = (const float*)d_in[1];
    const float* Wbr = (const float*)d_in[2];
    const float* Wbs = (const float*)d_in[3];
    const float* Wcr = (const float*)d_in[4];
    const float* Wcm = (const float*)d_in[5];
    const float* Dv  = (const float*)d_in[6];
    float* out = (float*)d_out;

    const int T = in_sizes[0] / D_MODEL;   // 16384

    cudaFuncSetAttribute(compute_E_kernel, cudaFuncAttributeMaxDynamicSharedMemorySize, E_SMEM);
    cudaFuncSetAttribute(gemm1_mma, cudaFuncAttributeMaxDynamicSharedMemorySize, G1_SMEM);
    cudaFuncSetAttribute(gemm2_mma, cudaFuncAttributeMaxDynamicSharedMemorySize, G2_SMEM);

    compute_E_kernel<<<E_CTAS, 256, E_SMEM>>>(Af, Wbs, Wcr);
    compute_F1t_kernel<<<32, 256>>>(Wbr);
    compute_Wcmt_kernel<<<32, 256>>>(Wcm);
    gemm1_mma<<<T / 64, 256, G1_SMEM>>>(u);
    gemm2_mma<<<(T / 64) * 4, 256, G2_SMEM>>>(u, Dv, out);
}

// round 16
// speedup vs baseline: 1.1989x; 1.1989x over previous
#include <cuda_runtime.h>
#include <cstdint>

typedef unsigned long long ull;
typedef unsigned int uint;

#define D_MODEL 2048
#define N_STATE 256
#define RANK    64
#define LEVELS  8
#define MAX_T   16384

#define E_CTAS 8
#define E_ROWS 8
#define E_SMEM ((N_STATE * RANK + E_ROWS * N_STATE) * (int)sizeof(float))

#define RSB 36         // B smem row stride in ull (32 data + 4 pad)
#define UST 68         // u smem row stride in floats (64 data + 4 pad)

// ---- gemm1 pipeline: 2 stages -> 71.7KB -> 2 CTAs/SM ----
#define NSTAGE 2
#define U_STAGE_B (64 * UST * 4)              // 17408
#define B_STAGE_B (64 * RSB * 8)              // 18432
#define STAGE_B   (U_STAGE_B + B_STAGE_B)     // 35840
#define G1_SMEM   (NSTAGE * STAGE_B)          // 71680

// ---- gemm2 smem ----
#define G2A_B (64 * RSB * 8)                  // 18432
#define G2B_B (128 * RSB * 8)                 // 36864
#define G2_SMEM (G2A_B + G2B_B)               // 55296

// scratch (plain, unpermuted layouts)
__device__ float g_E[RANK * RANK];
__device__ ull g_F1t[RANK * (D_MODEL / 2)];     // [n][kw] (hi bf16x2 | lo<<32)
__device__ ull g_Wt[D_MODEL * (RANK / 2)];      // [n][kw], Wt[n][k]=Wcm[k][n]
__device__ ull g_t[MAX_T * (RANK / 2)];         // [row][kw]

// =====================================================================
// helpers
// =====================================================================
__device__ __forceinline__ ull split2(float x0, float x1) {
    uint hh;
    asm("cvt.rn.bf16x2.f32 %0, %1, %2;" : "=r"(hh) : "f"(x1), "f"(x0));
    float h0 = __uint_as_float(hh << 16);
    float h1 = __uint_as_float(hh & 0xffff0000u);
    uint ll;
    asm("cvt.rn.bf16x2.f32 %0, %1, %2;" : "=r"(ll) : "f"(x1 - h1), "f"(x0 - h0));
    return (ull)hh | ((ull)ll << 32);
}

__device__ __forceinline__ void mma16816(float* d, uint a0, uint a1, uint a2, uint a3,
                                         uint b0, uint b1) {
    asm volatile(
        "mma.sync.aligned.m16n8k16.row.col.f32.bf16.bf16.f32 "
        "{%0,%1,%2,%3}, {%4,%5,%6,%7}, {%8,%9}, {%0,%1,%2,%3};"
        : "+f"(d[0]), "+f"(d[1]), "+f"(d[2]), "+f"(d[3])
        : "r"(a0), "r"(a1), "r"(a2), "r"(a3), "r"(b0), "r"(b1));
}

__device__ __forceinline__ uint smem_u32(const void* p) {
    uint a;
    asm("{ .reg .u64 t; cvta.to.shared.u64 t, %1; cvt.u32.u64 %0, t; }" : "=r"(a) : "l"(p));
    return a;
}
__device__ __forceinline__ void cp_async16(uint dst, const void* src) {
    asm volatile("cp.async.cg.shared.global [%0], [%1], 16;" :: "r"(dst), "l"(src));
}
#define CP_COMMIT() asm volatile("cp.async.commit_group;" ::: "memory")
#define CP_WAIT(n)  asm volatile("cp.async.wait_group %0;" :: "n"(n) : "memory")

// =====================================================================
// Kernel 0: E = Wbs @ Butterfly @ Wcr   (64x64)
// =====================================================================
__global__ __launch_bounds__(256) void compute_E_kernel(const float* __restrict__ A_factors,
                                                        const float* __restrict__ Wbs,
                                                        const float* __restrict__ Wcr) {
    extern __shared__ float esm[];
    float* Wcr_s = esm;
    float* G     = esm + N_STATE * RANK;
    __shared__ float Af[LEVELS * 4];
    const int tid = threadIdx.x;
    const int r0 = blockIdx.x * E_ROWS;
    if (tid < LEVELS * 4) Af[tid] = A_factors[tid];

    for (int i = tid; i < N_STATE * RANK / 4; i += 256)
        ((float4*)Wcr_s)[i] = ((const float4*)Wcr)[i];
    for (int i = tid; i < E_ROWS * N_STATE / 4; i += 256)
        ((float4*)G)[i] = ((const float4*)(Wbs + (size_t)r0 * N_STATE))[i];
    __syncthreads();

#pragma unroll
    for (int lvl = 0; lvl < LEVELS; lvl++) {
        const int stride = 128 >> lvl;
        const float a00 = Af[lvl * 4 + 0], a01 = Af[lvl * 4 + 1];
        const float a10 = Af[lvl * 4 + 2], a11 = Af[lvl * 4 + 3];
#pragma unroll
        for (int p = tid; p < E_ROWS * 128; p += 256) {
            int r  = p >> 7;
            int pi = p & 127;
            int low = pi & (stride - 1);
            int n0  = ((pi - low) << 1) | low;
            int n1  = n0 + stride;
            float x0 = G[r * N_STATE + n0];
            float x1 = G[r * N_STATE + n1];
            G[r * N_STATE + n0] = x0 * a00 + x1 * a10;
            G[r * N_STATE + n1] = x0 * a01 + x1 * a11;
        }
        __syncthreads();
    }

    for (int o = tid; o < E_ROWS * RANK; o += 256) {
        int r = o >> 6, j = o & 63;
        float acc = 0.f;
#pragma unroll 8
        for (int n = 0; n < N_STATE; n++)
            acc += G[r * N_STATE + n] * Wcr_s[n * RANK + j];
        g_E[(r0 + r) * RANK + j] = acc;
    }
}

// =====================================================================
// Kernel 1: F1t[n][kw] = hi/lo split of (Wbr @ E)^T. (conflict-free)
// =====================================================================
__global__ __launch_bounds__(256) void compute_F1t_kernel(const float* __restrict__ Wbr) {
    __shared__ float Wst[64 * 65];   // [r][k_local]
    __shared__ float Es[64 * 64];
    __shared__ float Fs[64 * 65];    // [n][k_local]
    const int tid = threadIdx.x;
    const int k0 = blockIdx.x * 64;

#pragma unroll
    for (int i = 0; i < 16; i++) {
        int idx = tid + i * 256;
        int k = idx >> 6, r = idx & 63;
        Wst[r * 65 + k] = Wbr[(size_t)(k0 + k) * 64 + r];
    }
#pragma unroll
    for (int i = 0; i < 4; i++)
        ((float4*)Es)[tid + i * 256] = ((const float4*)g_E)[tid + i * 256];
    __syncthreads();

    const int k = tid & 63, nq = tid >> 6;
#pragma unroll
    for (int nn = 0; nn < 16; nn++) {
        int n = nq * 16 + nn;
        float acc = 0.f;
#pragma unroll 8
        for (int r = 0; r < 64; r++)
            acc += Wst[r * 65 + k] * Es[r * 64 + n];
        Fs[n * 65 + k] = acc;
    }
    __syncthreads();

#pragma unroll
    for (int i = 0; i < 8; i++) {
        int idx = tid + i * 256;
        int n = idx >> 5, kw = idx & 31;
        g_F1t[(size_t)n * (D_MODEL / 2) + blockIdx.x * 32 + kw] =
            split2(Fs[n * 65 + 2 * kw], Fs[n * 65 + 2 * kw + 1]);
    }
}

// =====================================================================
// Kernel 1b: Wt[n][kw] = hi/lo split of Wcm^T.
// =====================================================================
__global__ __launch_bounds__(256) void compute_Wcmt_kernel(const float* __restrict__ Wcm) {
    __shared__ float S[64 * 65];
    const int tid = threadIdx.x;
    const int n0 = blockIdx.x * 64;
#pragma unroll
    for (int it = 0; it < 16; it++) {
        int idx = it * 256 + tid;
        int k = idx >> 6, nn = idx & 63;
        S[nn * 65 + k] = Wcm[(size_t)k * D_MODEL + n0 + nn];
    }
    __syncthreads();
#pragma unroll
    for (int it = 0; it < 8; it++) {
        int idx = it * 256 + tid;
        int nn = idx >> 5, kw = idx & 31;
        g_Wt[(size_t)(n0 + nn) * 32 + kw] = split2(S[nn * 65 + 2 * kw], S[nn * 65 + 2 * kw + 1]);
    }
}

// =====================================================================
// Kernel 2: GEMM1: t = u @ F1.  M=64/CTA, K=2048 (32 chunks of 64).
// 8 warps = 4 m-groups x 2 K-parities (convert-once). 2-stage pipeline
// (71.7KB smem) -> 2 CTAs/SM. R16 FIX: tail iterations use CP_WAIT(0)
// because with <2 groups in flight CP_WAIT(1) is a no-op (R15 race).
// =====================================================================
__global__ __launch_bounds__(256, 2) void gemm1_mma(const float* __restrict__ u) {
    extern __shared__ char dsm[];
    const int tid = threadIdx.x;
    const int lane = tid & 31;
    const int w = tid >> 5;                  // 0..7
    const int g = lane >> 2, c = lane & 3;
    const int m0 = (w & 3) * 16;
    const int kpar = w >> 2;                 // 0: even chunks, 1: odd chunks
    const size_t row0 = (size_t)blockIdx.x * 64;

    const uint sbase = smem_u32(dsm);
    const int lr = tid >> 4, lseg = tid & 15;

    float acc[8][4];
#pragma unroll
    for (int i = 0; i < 8; i++)
#pragma unroll
        for (int j = 0; j < 4; j++) acc[i][j] = 0.f;

    auto issue = [&](int ch, int s) {
        const uint ub = sbase + (uint)s * STAGE_B;
        const uint bb = ub + U_STAGE_B;
        const float* usrc = u + (row0 + lr) * D_MODEL + ch * 64 + lseg * 4;
        const ull* bsrc = g_F1t + (size_t)lr * (D_MODEL / 2) + ch * 32 + lseg * 2;
#pragma unroll
        for (int j = 0; j < 4; j++) {
            cp_async16(ub + (uint)((lr + j * 16) * UST * 4 + lseg * 16),
                       usrc + (size_t)(j * 16) * D_MODEL);
            cp_async16(bb + (uint)((lr + j * 16) * RSB * 8 + lseg * 16),
                       bsrc + (size_t)(j * 16) * (D_MODEL / 2));
        }
        CP_COMMIT();
    };

    issue(0, 0);
    issue(1, 1);

    for (int ch = 0; ch < 32; ch++) {
        // Steady state: 2 groups pending -> CP_WAIT(1) guarantees current
        // stage. Tail (ch>=30): only 1 group may remain pending, so
        // CP_WAIT(1) would be a no-op -> must drain fully.
        if (ch < 30) { CP_WAIT(1); } else { CP_WAIT(0); }
        __syncthreads();

        if ((ch & 1) == kpar) {
            const float* Us = (const float*)(dsm + (ch & 1) * STAGE_B);
            const ull* Bs = (const ull*)(dsm + (ch & 1) * STAGE_B + U_STAGE_B);
#pragma unroll
            for (int ks = 0; ks < 4; ks++) {
                float2 f0 = *(const float2*)&Us[(m0 + g) * UST + ks * 16 + c * 2];
                float2 f1 = *(const float2*)&Us[(m0 + g + 8) * UST + ks * 16 + c * 2];
                float2 f2 = *(const float2*)&Us[(m0 + g) * UST + ks * 16 + 8 + c * 2];
                float2 f3 = *(const float2*)&Us[(m0 + g + 8) * UST + ks * 16 + 8 + c * 2];
                ull A0 = split2(f0.x, f0.y), A1 = split2(f1.x, f1.y);
                ull A2 = split2(f2.x, f2.y), A3 = split2(f3.x, f3.y);
                uint ah0 = (uint)A0, al0 = (uint)(A0 >> 32);
                uint ah1 = (uint)A1, al1 = (uint)(A1 >> 32);
                uint ah2 = (uint)A2, al2 = (uint)(A2 >> 32);
                uint ah3 = (uint)A3, al3 = (uint)(A3 >> 32);
#pragma unroll
                for (int nh = 0; nh < 2; nh++) {
                    ull b0[4], b1[4];
#pragma unroll
                    for (int i = 0; i < 4; i++) {
                        int nt = nh * 4 + i;
                        b0[i] = Bs[(nt * 8 + g) * RSB + ks * 8 + c];
                        b1[i] = Bs[(nt * 8 + g) * RSB + ks * 8 + 4 + c];
                    }
#pragma unroll
                    for (int i = 0; i < 4; i++)
                        mma16816(acc[nh * 4 + i], ah0, ah1, ah2, ah3,
                                 (uint)b0[i], (uint)b1[i]);
#pragma unroll
                    for (int i = 0; i < 4; i++)
                        mma16816(acc[nh * 4 + i], ah0, ah1, ah2, ah3,
                                 (uint)(b0[i] >> 32), (uint)(b1[i] >> 32));
#pragma unroll
                    for (int i = 0; i < 4; i++)
                        mma16816(acc[nh * 4 + i], al0, al1, al2, al3,
                                 (uint)b0[i], (uint)b1[i]);
                }
            }
        }
        __syncthreads();   // all warps done with stage ch before refill
        if (ch + 2 < 32) issue(ch + 2, ch & 1);
    }

    // combine K-parity partials (padded stride 33 -> conflict-free)
    float* Red = (float*)dsm;
    if (kpar == 1) {
#pragma unroll
        for (int nt = 0; nt < 8; nt++)
#pragma unroll
            for (int j = 0; j < 4; j++)
                Red[((w & 3) * 32 + lane) * 33 + nt * 4 + j] = acc[nt][j];
    }
    __syncthreads();
    if (kpar == 0) {
#pragma unroll
        for (int nt = 0; nt < 8; nt++)
#pragma unroll
            for (int j = 0; j < 4; j++)
                acc[nt][j] += Red[((w & 3) * 32 + lane) * 33 + nt * 4 + j];

        // epilogue: t as hi/lo bf16 word pairs (fragment-compatible layout)
#pragma unroll
        for (int nt = 0; nt < 8; nt++) {
            int kw = nt * 4 + c;
            size_t r = row0 + m0 + g;
            g_t[r * 32 + kw]       = split2(acc[nt][0], acc[nt][1]);
            g_t[(r + 8) * 32 + kw] = split2(acc[nt][2], acc[nt][3]);
        }
    }
}

// =====================================================================
// Kernel 3: GEMM2: out = t @ Wcm + D*u.  Tile 64x128, grid 4096.
// [R13 version, measured best] cp.async burst staging, MMA from smem,
// Dsm-overlay epilogue with batched u loads (MLP=8) + hoisted Dv.
// =====================================================================
__global__ __launch_bounds__(256) void gemm2_mma(const float* __restrict__ u,
                                                 const float* __restrict__ Dv,
                                                 float* __restrict__ out) {
    extern __shared__ char dsm[];
    ull* Asm = (ull*)dsm;                    // [64 * RSB]
    ull* Bsm = (ull*)(dsm + G2A_B);          // [128 * RSB]
    float* Dsm = (float*)dsm;                // [64][132] overlay after compute

    const int tid = threadIdx.x;
    const int lane = tid & 31;
    const int w = tid >> 5;
    const int g = lane >> 2, c = lane & 3;
    const int m0 = (w & 3) * 16;
    const int n0b = (w >> 2) * 64;
    const int ct = blockIdx.x & 15;
    const int rt = blockIdx.x >> 4;
    const size_t row0 = (size_t)rt * 64;
    const int col0 = ct * 128;

    {
        const uint ab = smem_u32(Asm);
        const uint bb = smem_u32(Bsm);
        const int lr = tid >> 4, lseg = tid & 15;
#pragma unroll
        for (int j = 0; j < 4; j++) {
            int r = lr + j * 16;
            cp_async16(ab + (uint)(r * RSB * 8 + lseg * 16),
                       g_t + (row0 + r) * 32 + lseg * 2);
        }
#pragma unroll
        for (int j = 0; j < 8; j++) {
            int n = lr + j * 16;
            cp_async16(bb + (uint)(n * RSB * 8 + lseg * 16),
                       g_Wt + (size_t)(col0 + n) * 32 + lseg * 2);
        }
        CP_COMMIT();
        CP_WAIT(0);
        __syncthreads();
    }

    ull afr[16];
#pragma unroll
    for (int ks = 0; ks < 4; ks++) {
        afr[ks * 4 + 0] = Asm[(m0 + g) * RSB + ks * 8 + c];
        afr[ks * 4 + 1] = Asm[(m0 + g + 8) * RSB + ks * 8 + c];
        afr[ks * 4 + 2] = Asm[(m0 + g) * RSB + ks * 8 + 4 + c];
        afr[ks * 4 + 3] = Asm[(m0 + g + 8) * RSB + ks * 8 + 4 + c];
    }

    float acc[8][4];
#pragma unroll
    for (int i = 0; i < 8; i++)
#pragma unroll
        for (int j = 0; j < 4; j++) acc[i][j] = 0.f;

#pragma unroll
    for (int ks = 0; ks < 4; ks++) {
        uint ah0 = (uint)afr[ks * 4 + 0], al0 = (uint)(afr[ks * 4 + 0] >> 32);
        uint ah1 = (uint)afr[ks * 4 + 1], al1 = (uint)(afr[ks * 4 + 1] >> 32);
        uint ah2 = (uint)afr[ks * 4 + 2], al2 = (uint)(afr[ks * 4 + 2] >> 32);
        uint ah3 = (uint)afr[ks * 4 + 3], al3 = (uint)(afr[ks * 4 + 3] >> 32);
        ull b0[8], b1[8];
#pragma unroll
        for (int nt = 0; nt < 8; nt++) {
            b0[nt] = Bsm[(n0b + nt * 8 + g) * RSB + ks * 8 + c];
            b1[nt] = Bsm[(n0b + nt * 8 + g) * RSB + ks * 8 + 4 + c];
        }
#pragma unroll
        for (int nt = 0; nt < 8; nt++)
            mma16816(acc[nt], ah0, ah1, ah2, ah3, (uint)b0[nt], (uint)b1[nt]);
#pragma unroll
        for (int nt = 0; nt < 8; nt++)
            mma16816(acc[nt], ah0, ah1, ah2, ah3,
                     (uint)(b0[nt] >> 32), (uint)(b1[nt] >> 32));
#pragma unroll
        for (int nt = 0; nt < 8; nt++)
            mma16816(acc[nt], al0, al1, al2, al3, (uint)b0[nt], (uint)b1[nt]);
    }
    __syncthreads();   // tiles consumed; Dsm may overlay

    // stage accumulators into Dsm
#pragma unroll
    for (int nt = 0; nt < 8; nt++) {
        int cc = n0b + nt * 8 + c * 2;
        *(float2*)&Dsm[(m0 + g) * 132 + cc]     = make_float2(acc[nt][0], acc[nt][1]);
        *(float2*)&Dsm[(m0 + g + 8) * 132 + cc] = make_float2(acc[nt][2], acc[nt][3]);
    }

    // batch ALL u loads now (acc regs dead, overlaps the sync below)
    const int er = tid >> 5, ec4 = tid & 31;
    const int gcol = col0 + ec4 * 4;
    const float4 dv = *(const float4*)(Dv + gcol);
    float4 uv[8];
#pragma unroll
    for (int it = 0; it < 8; it++) {
        uv[it] = *(const float4*)(u + (row0 + er + it * 8) * D_MODEL + gcol);
    }
    __syncthreads();

#pragma unroll
    for (int it = 0; it < 8; it++) {
        int r = er + it * 8;
        float4 o;
        o.x = Dsm[r * 132 + ec4 * 4 + 0] + dv.x * uv[it].x;
        o.y = Dsm[r * 132 + ec4 * 4 + 1] + dv.y * uv[it].y;
        o.z = Dsm[r * 132 + ec4 * 4 + 2] + dv.z * uv[it].z;
        o.w = Dsm[r * 132 + ec4 * 4 + 3] + dv.w * uv[it].w;
        *(float4*)(out + (row0 + r) * D_MODEL + gcol) = o;
    }
}

extern "C" void kernel_launch(void* const* d_in, const int* in_sizes, int n_in,
                              void* d_out, int out_size) {
    const float* u   = (const float*)d_in[0];
    const float* Af  = (const float*)d_in[1];
    const float* Wbr = (const float*)d_in[2];
    const float* Wbs = (const float*)d_in[3];
    const float* Wcr = (const float*)d_in[4];
    const float* Wcm = (const float*)d_in[5];
    const float* Dv  = (const float*)d_in[6];
    float* out = (float*)d_out;

    const int T = in_sizes[0] / D_MODEL;   // 16384

    cudaFuncSetAttribute(compute_E_kernel, cudaFuncAttributeMaxDynamicSharedMemorySize, E_SMEM);
    cudaFuncSetAttribute(gemm1_mma, cudaFuncAttributeMaxDynamicSharedMemorySize, G1_SMEM);
    cudaFuncSetAttribute(gemm2_mma, cudaFuncAttributeMaxDynamicSharedMemorySize, G2_SMEM);

    compute_E_kernel<<<E_CTAS, 256, E_SMEM>>>(Af, Wbs, Wcr);
    compute_F1t_kernel<<<32, 256>>>(Wbr);
    compute_Wcmt_kernel<<<32, 256>>>(Wcm);
    gemm1_mma<<<T / 64, 256, G1_SMEM>>>(u);
    gemm2_mma<<<(T / 64) * (D_MODEL / 128), 256, G2_SMEM>>>(u, Dv, out);
}